// round 17
// baseline (speedup 1.0000x reference)
#include <cuda_runtime.h>

#define BB 8192
#define TT 256
#define FF 16
#define HH 8
#define FUT 8

typedef unsigned long long u64;

__device__ __forceinline__ float tanhm(float x) {
    float y;
    asm("tanh.approx.f32 %0, %1;" : "=f"(y) : "f"(x));
    return y;
}
__device__ __forceinline__ float sigm(float x) {
    return fmaf(0.5f, tanhm(0.5f * x), 0.5f);
}
__device__ __forceinline__ u64 ffma2(u64 a, u64 b, u64 c) {
    u64 d;
    asm("fma.rn.f32x2 %0, %1, %2, %3;" : "=l"(d) : "l"(a), "l"(b), "l"(c));
    return d;
}
__device__ __forceinline__ u64 pack2(float lo, float hi) {
    u64 r;
    asm("mov.b64 %0, {%1, %2};" : "=l"(r) : "f"(lo), "f"(hi));
    return r;
}
__device__ __forceinline__ float hsum2(u64 v) {
    float lo, hi;
    asm("mov.b64 {%0, %1}, %2;" : "=f"(lo), "=f"(hi) : "l"(v));
    return lo + hi;
}
__device__ __forceinline__ float2 unpack2(u64 v) {
    float lo, hi;
    asm("mov.b64 {%0, %1}, %2;" : "=f"(lo), "=f"(hi) : "l"(v));
    return make_float2(lo, hi);
}
__device__ __forceinline__ void cpa16(unsigned dst, const void* src) {
    asm volatile("cp.async.ca.shared.global [%0], [%1], 16;\n"
                 :: "r"(dst), "l"(src) : "memory");
}
__device__ __forceinline__ void cpa_commit() {
    asm volatile("cp.async.commit_group;\n" ::: "memory");
}
__device__ __forceinline__ void cpa_wait3() {
    asm volatile("cp.async.wait_group 3;\n" ::: "memory");
}

// 1 element per 8-thread group, 128-thread blocks, 512 blocks (single wave,
// 13.8 warps/SM = 3.46/SMSP). All weights in smem (broadcast LDS.128).
// x via 4-deep warp-local cp.async ring (zero x registers). FFMA2 k2-paired.
// __launch_bounds__(128, 4): reg cap 128, natural demand ~110 -> no spill.

__global__ __launch_bounds__(128, 4) void LSTM_91122026152229_kernel(
    const float* __restrict__ past,   // [B,T,F]
    const float* __restrict__ fut,    // [B,FUT]
    const float* __restrict__ W1, const float* __restrict__ U1, const float* __restrict__ b1,
    const float* __restrict__ W2, const float* __restrict__ U2, const float* __restrict__ b2,
    const float* __restrict__ Wd1, const float* __restrict__ bd1,
    const float* __restrict__ Wd2, const float* __restrict__ bd2,
    const float* __restrict__ Wo, const float* __restrict__ bo,
    float* __restrict__ out)          // [B,4]
{
    __shared__ ulonglong2 sW1if[8 * 8], sW1go[8 * 8];   // k2=0..7
    __shared__ ulonglong2 sU1if[4 * 8], sU1go[4 * 8];   // k2=0..3
    __shared__ ulonglong2 sW2if[4 * 8], sW2go[4 * 8];
    __shared__ ulonglong2 sU2if[4 * 8], sU2go[4 * 8];
    // x ring: 4 slots x 16 elems x 20 floats (80B stride, conflict-free)
    __shared__ __align__(16) float sx[4 * 16 * 20];

    const int tid = threadIdx.x;

    // repack W1 (512 floats): src i = f*32 + g*8 + u
    for (int i = tid; i < 512; i += 128) {
        int f = i >> 5, r = i & 31, gg = r >> 3, uu = r & 7;
        int k2 = f >> 1, odd = f & 1;
        float v = W1[i];
        if (gg < 2)
            ((float*)sW1if)[((k2 * 8 + uu) << 2) + gg * 2 + odd] = v;
        else
            ((float*)sW1go)[((k2 * 8 + uu) << 2) + (gg - 2) * 2 + odd] = v;
    }
    // repack U1, W2, U2 (256 floats each)
    for (int i = tid; i < 256; i += 128) {
        int k = i >> 5, r = i & 31, gg = r >> 3, uu = r & 7;
        int k2 = k >> 1, odd = k & 1;
        int fo = ((k2 * 8 + uu) << 2) + ((gg & 1) * 2) + odd;
        float vU1 = U1[i], vW2 = W2[i], vU2 = U2[i];
        if (gg < 2) {
            ((float*)sU1if)[fo] = vU1;
            ((float*)sW2if)[fo] = vW2;
            ((float*)sU2if)[fo] = vU2;
        } else {
            ((float*)sU1go)[fo] = vU1;
            ((float*)sW2go)[fo] = vW2;
            ((float*)sU2go)[fo] = vU2;
        }
    }
    __syncthreads();

    const int el    = tid >> 3;            // block-local element 0..15
    const int u     = tid & 7;
    const int lane  = tid & 31;
    const int base8 = lane & 24;
    const int e     = blockIdx.x * 16 + el;   // global element

    const float bi1 = b1[u], bf1 = b1[u + 8], bg1 = b1[u + 16], bq1 = b1[u + 24];
    const float bi2 = b2[u], bf2 = b2[u + 8], bg2 = b2[u + 16], bq2 = b2[u + 24];

    // cp.async producer: lanes u<4 of each group load their element's chunk u
    const float* gsrc = past + (size_t)e * (TT * FF) + u * 4;
    const unsigned sxa  = (unsigned)__cvta_generic_to_shared(sx);
    const unsigned pdst = sxa + (unsigned)(el * 20 + u * 4) * 4u;

    #pragma unroll
    for (int s = 0; s < 3; s++) {
        if (u < 4) cpa16(pdst + (unsigned)(s * 320 * 4), gsrc + s * 16);
        cpa_commit();
    }

    float h1 = 0.f, c1 = 0.f, h2 = 0.f, c2 = 0.f;
    u64 hp1[4], hp2[4];
    #pragma unroll
    for (int j = 0; j < 4; j++) { hp1[j] = 0ULL; hp2[j] = 0ULL; }

    #pragma unroll 1
    for (int t = 0; t < TT; t++) {
        // produce x for step t+3
        const int tn = (t + 3 < TT) ? (t + 3) : (TT - 1);
        if (u < 4) cpa16(pdst + (unsigned)(((t + 3) & 3) * 320 * 4), gsrc + tn * 16);
        cpa_commit();
        cpa_wait3();
        __syncwarp();

        // consume x[t]: 4 LDS.128 on this group's row (broadcast in group)
        const ulonglong2* xr = (const ulonglong2*)(sx + (t & 3) * 320 + el * 20);
        const ulonglong2 x0 = xr[0], x1 = xr[1], x2 = xr[2], x3 = xr[3];
        const u64 xq[8] = { x0.x, x0.y, x1.x, x1.y, x2.x, x2.y, x3.x, x3.y };

        // ---- layer 1 ----
        u64 ai = 0, af = 0, ag = 0, ao = 0;
        #pragma unroll
        for (int k2 = 0; k2 < 8; k2++) {
            const ulonglong2 wif = sW1if[k2 * 8 + u];
            const ulonglong2 wgo = sW1go[k2 * 8 + u];
            const u64 xv = xq[k2];
            ai = ffma2(xv, wif.x, ai);
            af = ffma2(xv, wif.y, af);
            ag = ffma2(xv, wgo.x, ag);
            ao = ffma2(xv, wgo.y, ao);
        }
        #pragma unroll
        for (int k2 = 0; k2 < 4; k2++) {
            const ulonglong2 wif = sU1if[k2 * 8 + u];
            const ulonglong2 wgo = sU1go[k2 * 8 + u];
            const u64 hv = hp1[k2];
            ai = ffma2(hv, wif.x, ai);
            af = ffma2(hv, wif.y, af);
            ag = ffma2(hv, wgo.x, ag);
            ao = ffma2(hv, wgo.y, ao);
        }
        {
            const float zi = hsum2(ai) + bi1;
            const float zf = hsum2(af) + bf1;
            const float zg = hsum2(ag) + bg1;
            const float zo = hsum2(ao) + bq1;
            c1 = fmaf(sigm(zf), c1, sigm(zi) * tanhm(zg));
            h1 = sigm(zo) * tanhm(c1);
        }
        #pragma unroll
        for (int k2 = 0; k2 < 4; k2++) {
            const float pa = __shfl_sync(0xffffffffu, h1, base8 + 2 * k2);
            const float pb = __shfl_sync(0xffffffffu, h1, base8 + 2 * k2 + 1);
            hp1[k2] = pack2(pa, pb);
        }

        // ---- layer 2 ----
        u64 yi = 0, yf = 0, yg = 0, yo = 0;
        #pragma unroll
        for (int k2 = 0; k2 < 4; k2++) {
            const ulonglong2 wif = sW2if[k2 * 8 + u];
            const ulonglong2 wgo = sW2go[k2 * 8 + u];
            const u64 hv = hp1[k2];
            yi = ffma2(hv, wif.x, yi);
            yf = ffma2(hv, wif.y, yf);
            yg = ffma2(hv, wgo.x, yg);
            yo = ffma2(hv, wgo.y, yo);
        }
        #pragma unroll
        for (int k2 = 0; k2 < 4; k2++) {
            const ulonglong2 wif = sU2if[k2 * 8 + u];
            const ulonglong2 wgo = sU2go[k2 * 8 + u];
            const u64 hv = hp2[k2];
            yi = ffma2(hv, wif.x, yi);
            yf = ffma2(hv, wif.y, yf);
            yg = ffma2(hv, wgo.x, yg);
            yo = ffma2(hv, wgo.y, yo);
        }
        {
            const float zi = hsum2(yi) + bi2;
            const float zf = hsum2(yf) + bf2;
            const float zg = hsum2(yg) + bg2;
            const float zo = hsum2(yo) + bq2;
            c2 = fmaf(sigm(zf), c2, sigm(zi) * tanhm(zg));
            h2 = sigm(zo) * tanhm(c2);
        }
        #pragma unroll
        for (int k2 = 0; k2 < 4; k2++) {
            const float pa = __shfl_sync(0xffffffffu, h2, base8 + 2 * k2);
            const float pb = __shfl_sync(0xffffffffu, h2, base8 + 2 * k2 + 1);
            hp2[k2] = pack2(pa, pb);
        }
    }

    // ---- MLP head ----
    float h2s[8];
    #pragma unroll
    for (int k2 = 0; k2 < 4; k2++) {
        const float2 p = unpack2(hp2[k2]);
        h2s[2 * k2] = p.x; h2s[2 * k2 + 1] = p.y;
    }

    float d1 = bd1[u];
    #pragma unroll
    for (int k = 0; k < 8; k++)
        d1 = fmaf(h2s[k], Wd1[k * 8 + u], d1);
    const float* __restrict__ fp = fut + (size_t)e * FUT;
    #pragma unroll
    for (int k = 0; k < 8; k++)
        d1 = fmaf(fp[k], Wd1[(8 + k) * 8 + u], d1);
    d1 = fmaxf(d1, 0.f);

    float d2 = bd2[u];
    #pragma unroll
    for (int k = 0; k < 8; k++) {
        const float d1k = __shfl_sync(0xffffffffu, d1, base8 + k);
        d2 = fmaf(d1k, Wd2[k * 8 + u], d2);
    }
    d2 = fmaxf(d2, 0.f);

    float o = (u < 4) ? bo[u] : 0.f;
    #pragma unroll
    for (int k = 0; k < 8; k++) {
        const float d2k = __shfl_sync(0xffffffffu, d2, base8 + k);
        if (u < 4) o = fmaf(d2k, Wo[k * 4 + u], o);
    }
    if (u < 4) out[(size_t)e * 4 + u] = o;
}

extern "C" void kernel_launch(void* const* d_in, const int* in_sizes, int n_in,
                              void* d_out, int out_size) {
    const float* past = (const float*)d_in[1];
    const float* fut  = (const float*)d_in[2];
    const float* W1   = (const float*)d_in[3];
    const float* U1   = (const float*)d_in[4];
    const float* b1   = (const float*)d_in[5];
    const float* W2   = (const float*)d_in[6];
    const float* U2   = (const float*)d_in[7];
    const float* b2   = (const float*)d_in[8];
    const float* Wd1  = (const float*)d_in[9];
    const float* bd1  = (const float*)d_in[10];
    const float* Wd2  = (const float*)d_in[11];
    const float* bd2  = (const float*)d_in[12];
    const float* Wo   = (const float*)d_in[13];
    const float* bo   = (const float*)d_in[14];

    // 65536 threads: 512 blocks x 128, 16 elems/block, single wave
    LSTM_91122026152229_kernel<<<BB / 16, 128>>>(
        past, fut, W1, U1, b1, W2, U2, b2, Wd1, bd1, Wd2, bd2, Wo, bo,
        (float*)d_out);
}